// round 2
// baseline (speedup 1.0000x reference)
#include <cuda_runtime.h>

#define B_  4
#define L_  1024
#define H_  16
#define D_  64
#define ND_ 1024

// Scratch (allocation-free rule: __device__ globals)
__device__ float g_q[B_*H_*L_*D_];                 // 16 MB, pre-scaled by 1/8
__device__ float g_k[B_*H_*L_*D_];                 // 16 MB
__device__ float g_v[B_*H_*L_*D_];                 // 16 MB
__device__ float g_bias[(size_t)B_*H_*L_*L_];      // 256 MB  [B,H,L,L]
__device__ float g_attn[B_*L_*ND_];                // 16 MB   [B,L,H*D]

// ---------------------------------------------------------------------------
// Kernel 1: QKV GEMM.  C[m,n] = dot(s[m,:], W_qkv[n,:]),  M=4096,N=3072,K=1024
// 128x128 tile, BK=16, 256 threads, 8x8 per thread. Scatter to q/k/v [B,H,L,D].
// ---------------------------------------------------------------------------
__global__ __launch_bounds__(256) void qkv_kernel(const float* __restrict__ A,
                                                  const float* __restrict__ W)
{
    const int K = ND_;
    __shared__ float As[16][128];
    __shared__ float Bs[16][128];
    int t  = threadIdx.x;
    int m0 = blockIdx.y * 128;
    int n0 = blockIdx.x * 128;
    int ty = t >> 4, tx = t & 15;

    float acc[8][8];
#pragma unroll
    for (int i = 0; i < 8; ++i)
#pragma unroll
        for (int j = 0; j < 8; ++j) acc[i][j] = 0.f;

    for (int kt = 0; kt < K; kt += 16) {
#pragma unroll
        for (int it = 0; it < 2; ++it) {
            int idx = t + it * 256;          // 0..511
            int row = idx >> 2;              // 0..127
            int c4  = (idx & 3) * 4;         // 0,4,8,12
            float4 av = *(const float4*)(A + (size_t)(m0 + row) * K + kt + c4);
            As[c4+0][row] = av.x; As[c4+1][row] = av.y;
            As[c4+2][row] = av.z; As[c4+3][row] = av.w;
            float4 bv = *(const float4*)(W + (size_t)(n0 + row) * K + kt + c4);
            Bs[c4+0][row] = bv.x; Bs[c4+1][row] = bv.y;
            Bs[c4+2][row] = bv.z; Bs[c4+3][row] = bv.w;
        }
        __syncthreads();
#pragma unroll
        for (int kk = 0; kk < 16; ++kk) {
            float a[8], b[8];
            *(float4*)(a)     = *(const float4*)&As[kk][ty*8];
            *(float4*)(a + 4) = *(const float4*)&As[kk][ty*8 + 4];
            *(float4*)(b)     = *(const float4*)&Bs[kk][tx*8];
            *(float4*)(b + 4) = *(const float4*)&Bs[kk][tx*8 + 4];
#pragma unroll
            for (int i = 0; i < 8; ++i)
#pragma unroll
                for (int j = 0; j < 8; ++j) acc[i][j] += a[i] * b[j];
        }
        __syncthreads();
    }

    // epilogue: n -> (part, h, d); 8 consecutive n stay in one (part,h)
    int nbase = n0 + tx * 8;
    int part  = nbase >> 10;
    int rem   = nbase & 1023;
    int h     = rem >> 6;
    int dbase = rem & 63;
    float scale = (part == 0) ? 0.125f : 1.0f;   // fold 1/sqrt(64) into q
    float* dst = (part == 0) ? g_q : ((part == 1) ? g_k : g_v);
#pragma unroll
    for (int i = 0; i < 8; ++i) {
        int m  = m0 + ty * 8 + i;
        int bb = m >> 10, si = m & 1023;
        float* o = dst + ((size_t)(bb * H_ + h) * L_ + si) * D_ + dbase;
        float4 v0 = make_float4(acc[i][0]*scale, acc[i][1]*scale,
                                acc[i][2]*scale, acc[i][3]*scale);
        float4 v1 = make_float4(acc[i][4]*scale, acc[i][5]*scale,
                                acc[i][6]*scale, acc[i][7]*scale);
        *(float4*)(o)     = v0;
        *(float4*)(o + 4) = v1;
    }
}

// ---------------------------------------------------------------------------
// Kernel 2: pair bias.  bias[b,h,i,j] = dot(z[b,i,j,:], W_bias[h,:]) + b_bias[h]
// Block = 128 consecutive (b,i,j) rows; z row in registers; W via broadcast LDS.
// ---------------------------------------------------------------------------
__global__ __launch_bounds__(256) void pairbias_kernel(const float* __restrict__ z,
                                                       const float* __restrict__ Wb,
                                                       const float* __restrict__ bb)
{
    __shared__ float zs[128 * 65];   // padded rows (65) -> conflict-free reads
    __shared__ float wbs[16 * 64];
    __shared__ float bbs[16];
    int t = threadIdx.x;
    size_t row0 = (size_t)blockIdx.x * 128;
    const float* zp = z + row0 * 64;

    for (int f = t; f < 2048; f += 256) {       // 8192 floats = 2048 float4
        float4 v = *(const float4*)(zp + (size_t)f * 4);
        int r = f >> 4, c = (f & 15) * 4;
        zs[r*65+c] = v.x; zs[r*65+c+1] = v.y; zs[r*65+c+2] = v.z; zs[r*65+c+3] = v.w;
    }
    for (int i = t; i < 1024; i += 256) wbs[i] = Wb[i];
    if (t < 16) bbs[t] = bb[t];
    __syncthreads();

    int j  = t & 127;
    int hb = (t >> 7) * 8;   // warps 0-3: h 0..7, warps 4-7: h 8..15

    float4 zr[16];
#pragma unroll
    for (int c4 = 0; c4 < 16; ++c4) {
        int c = c4 * 4;
        zr[c4] = make_float4(zs[j*65+c], zs[j*65+c+1], zs[j*65+c+2], zs[j*65+c+3]);
    }
    float acc[8];
#pragma unroll
    for (int hh = 0; hh < 8; ++hh) acc[hh] = bbs[hb + hh];
#pragma unroll
    for (int c4 = 0; c4 < 16; ++c4) {
        float4 zv = zr[c4];
#pragma unroll
        for (int hh = 0; hh < 8; ++hh) {
            float4 wv = *(const float4*)(wbs + (hb + hh) * 64 + c4 * 4);
            acc[hh] += zv.x*wv.x + zv.y*wv.y + zv.z*wv.z + zv.w*wv.w;
        }
    }

    size_t bi = row0 >> 10;                  // (b*L + i)
    int j0 = (int)(row0 & 1023);
    int bbatch = (int)(bi >> 10);
    int irow   = (int)(bi & 1023);
#pragma unroll
    for (int hh = 0; hh < 8; ++hh) {
        int h = hb + hh;
        g_bias[((size_t)(bbatch * H_ + h) * L_ + irow) * L_ + j0 + j] = acc[hh];
    }
}

// ---------------------------------------------------------------------------
// Kernel 3: flash attention with additive bias, fp32, online softmax.
// One block per (b, h, 64-row q block). k-tiles of 64. 256 threads: ty=q/4, tx.
// Dynamic smem: Qs,Ks,Vs,Ps each 64x65 floats = 66560 B.
// ---------------------------------------------------------------------------
__global__ __launch_bounds__(256) void attn_kernel()
{
    extern __shared__ float sm[];
    float* Qs = sm;
    float* Ks = sm + 4160;
    float* Vs = sm + 8320;
    float* Ps = sm + 12480;

    int t  = threadIdx.x;
    int ty = t >> 4, tx = t & 15;
    int blk = blockIdx.x;
    int qb = blk & 15;
    int h  = (blk >> 4) & 15;
    int b  = blk >> 8;
    size_t bh = (size_t)b * H_ + h;

    const float* qp = g_q + (bh * L_ + (size_t)qb * 64) * D_;
    for (int f = t; f < 1024; f += 256) {
        float4 v = *(const float4*)(qp + f * 4);
        int r = f >> 4, c = (f & 15) * 4;
        Qs[r*65+c] = v.x; Qs[r*65+c+1] = v.y; Qs[r*65+c+2] = v.z; Qs[r*65+c+3] = v.w;
    }

    float O[4][4];
    float m_i[4], l_i[4];
#pragma unroll
    for (int i = 0; i < 4; ++i) {
        m_i[i] = -1e30f; l_i[i] = 0.f;
#pragma unroll
        for (int j = 0; j < 4; ++j) O[i][j] = 0.f;
    }
    const float* bp = g_bias + (bh * L_ + (size_t)qb * 64) * L_;

    for (int kb = 0; kb < 16; ++kb) {
        __syncthreads();   // previous PV done before overwriting Ks/Vs/Ps
        const float* kp = g_k + (bh * L_ + (size_t)kb * 64) * D_;
        const float* vp = g_v + (bh * L_ + (size_t)kb * 64) * D_;
        for (int f = t; f < 1024; f += 256) {
            int r = f >> 4, c = (f & 15) * 4;
            float4 kv = *(const float4*)(kp + f * 4);
            Ks[r*65+c] = kv.x; Ks[r*65+c+1] = kv.y; Ks[r*65+c+2] = kv.z; Ks[r*65+c+3] = kv.w;
            float4 vv = *(const float4*)(vp + f * 4);
            Vs[r*65+c] = vv.x; Vs[r*65+c+1] = vv.y; Vs[r*65+c+2] = vv.z; Vs[r*65+c+3] = vv.w;
        }
        __syncthreads();

        // S = Q * K^T  (q already scaled by 1/8)
        float S[4][4];
#pragma unroll
        for (int i = 0; i < 4; ++i)
#pragma unroll
            for (int j = 0; j < 4; ++j) S[i][j] = 0.f;
#pragma unroll 8
        for (int d = 0; d < 64; ++d) {
            float qa[4], kv[4];
#pragma unroll
            for (int i = 0; i < 4; ++i) qa[i] = Qs[(ty*4 + i) * 65 + d];
#pragma unroll
            for (int j = 0; j < 4; ++j) kv[j] = Ks[(tx*4 + j) * 65 + d];
#pragma unroll
            for (int i = 0; i < 4; ++i)
#pragma unroll
                for (int j = 0; j < 4; ++j) S[i][j] += qa[i] * kv[j];
        }

        // bias + online softmax, row-wise over the 16-lane tx group
#pragma unroll
        for (int i = 0; i < 4; ++i) {
            const float* brow = bp + (size_t)(ty*4 + i) * L_ + kb * 64 + tx * 4;
            float s0 = S[i][0] + brow[0];
            float s1 = S[i][1] + brow[1];
            float s2 = S[i][2] + brow[2];
            float s3 = S[i][3] + brow[3];
            float mx = fmaxf(fmaxf(s0, s1), fmaxf(s2, s3));
#pragma unroll
            for (int o = 8; o; o >>= 1)
                mx = fmaxf(mx, __shfl_xor_sync(0xffffffffu, mx, o));
            float newm = fmaxf(m_i[i], mx);
            float corr = __expf(m_i[i] - newm);
            float p0 = __expf(s0 - newm);
            float p1 = __expf(s1 - newm);
            float p2 = __expf(s2 - newm);
            float p3 = __expf(s3 - newm);
            float rs = p0 + p1 + p2 + p3;
#pragma unroll
            for (int o = 8; o; o >>= 1)
                rs += __shfl_xor_sync(0xffffffffu, rs, o);
            l_i[i] = l_i[i] * corr + rs;
            m_i[i] = newm;
            O[i][0] *= corr; O[i][1] *= corr; O[i][2] *= corr; O[i][3] *= corr;
            int qr = ty*4 + i;
            Ps[qr*65 + tx*4 + 0] = p0;
            Ps[qr*65 + tx*4 + 1] = p1;
            Ps[qr*65 + tx*4 + 2] = p2;
            Ps[qr*65 + tx*4 + 3] = p3;
        }
        __syncthreads();

        // O += P * V
#pragma unroll 8
        for (int kk = 0; kk < 64; ++kk) {
            float pv[4], vv[4];
#pragma unroll
            for (int i = 0; i < 4; ++i) pv[i] = Ps[(ty*4 + i) * 65 + kk];
#pragma unroll
            for (int j = 0; j < 4; ++j) vv[j] = Vs[kk*65 + tx*4 + j];
#pragma unroll
            for (int i = 0; i < 4; ++i)
#pragma unroll
                for (int j = 0; j < 4; ++j) O[i][j] += pv[i] * vv[j];
        }
    }

#pragma unroll
    for (int i = 0; i < 4; ++i) {
        float inv = 1.0f / l_i[i];
        int qi = qb * 64 + ty*4 + i;
        float* op = g_attn + ((size_t)b * L_ + qi) * ND_ + h * D_ + tx * 4;
        float4 v = make_float4(O[i][0]*inv, O[i][1]*inv, O[i][2]*inv, O[i][3]*inv);
        *(float4*)op = v;
    }
}

// ---------------------------------------------------------------------------
// Kernel 4: output projection.  out[m,n] = dot(attn[m,:], W_out[n,:]) + b_out[n]
// Same GEMM structure as kernel 1.  M=4096, N=1024, K=1024.
// ---------------------------------------------------------------------------
__global__ __launch_bounds__(256) void proj_kernel(const float* __restrict__ Wout,
                                                   const float* __restrict__ bout,
                                                   float* __restrict__ out)
{
    const int K = ND_;
    const float* A = g_attn;
    __shared__ float As[16][128];
    __shared__ float Bs[16][128];
    int t  = threadIdx.x;
    int m0 = blockIdx.y * 128;
    int n0 = blockIdx.x * 128;
    int ty = t >> 4, tx = t & 15;

    float acc[8][8];
#pragma unroll
    for (int i = 0; i < 8; ++i)
#pragma unroll
        for (int j = 0; j < 8; ++j) acc[i][j] = 0.f;

    for (int kt = 0; kt < K; kt += 16) {
#pragma unroll
        for (int it = 0; it < 2; ++it) {
            int idx = t + it * 256;
            int row = idx >> 2;
            int c4  = (idx & 3) * 4;
            float4 av = *(const float4*)(A + (size_t)(m0 + row) * K + kt + c4);
            As[c4+0][row] = av.x; As[c4+1][row] = av.y;
            As[c4+2][row] = av.z; As[c4+3][row] = av.w;
            float4 bv = *(const float4*)(Wout + (size_t)(n0 + row) * K + kt + c4);
            Bs[c4+0][row] = bv.x; Bs[c4+1][row] = bv.y;
            Bs[c4+2][row] = bv.z; Bs[c4+3][row] = bv.w;
        }
        __syncthreads();
#pragma unroll
        for (int kk = 0; kk < 16; ++kk) {
            float a[8], b[8];
            *(float4*)(a)     = *(const float4*)&As[kk][ty*8];
            *(float4*)(a + 4) = *(const float4*)&As[kk][ty*8 + 4];
            *(float4*)(b)     = *(const float4*)&Bs[kk][tx*8];
            *(float4*)(b + 4) = *(const float4*)&Bs[kk][tx*8 + 4];
#pragma unroll
            for (int i = 0; i < 8; ++i)
#pragma unroll
                for (int j = 0; j < 8; ++j) acc[i][j] += a[i] * b[j];
        }
        __syncthreads();
    }

    int nb = n0 + tx * 8;
    float4 bi0 = *(const float4*)(bout + nb);
    float4 bi1 = *(const float4*)(bout + nb + 4);
#pragma unroll
    for (int i = 0; i < 8; ++i) {
        int m = m0 + ty * 8 + i;
        float* o = out + (size_t)m * ND_ + nb;
        float4 v0 = make_float4(acc[i][0]+bi0.x, acc[i][1]+bi0.y,
                                acc[i][2]+bi0.z, acc[i][3]+bi0.w);
        float4 v1 = make_float4(acc[i][4]+bi1.x, acc[i][5]+bi1.y,
                                acc[i][6]+bi1.z, acc[i][7]+bi1.w);
        *(float4*)(o)     = v0;
        *(float4*)(o + 4) = v1;
    }
}

// ---------------------------------------------------------------------------
extern "C" void kernel_launch(void* const* d_in, const int* in_sizes, int n_in,
                              void* d_out, int out_size)
{
    const float* s      = (const float*)d_in[0];
    const float* z      = (const float*)d_in[1];
    const float* W_qkv  = (const float*)d_in[2];
    const float* W_bias = (const float*)d_in[3];
    const float* b_bias = (const float*)d_in[4];
    const float* W_out  = (const float*)d_in[5];
    const float* b_out  = (const float*)d_in[6];
    float* out = (float*)d_out;

    (void)in_sizes; (void)n_in; (void)out_size;

    cudaFuncSetAttribute(attn_kernel,
                         cudaFuncAttributeMaxDynamicSharedMemorySize, 66560);

    dim3 g1(24, 32);
    qkv_kernel<<<g1, 256>>>(s, W_qkv);

    pairbias_kernel<<<32768, 256>>>(z, W_bias, b_bias);

    attn_kernel<<<1024, 256, 66560>>>();

    dim3 g4(8, 32);
    proj_kernel<<<g4, 256>>>(W_out, b_out, out);
}

// round 3
// speedup vs baseline: 1.1169x; 1.1169x over previous
#include <cuda_runtime.h>
#include <stdint.h>

#define B_  4
#define L_  1024
#define H_  16
#define D_  64
#define ND_ 1024

// Scratch (allocation-free rule: __device__ globals)
__device__ float g_q[B_*H_*L_*D_];                 // 16 MB, pre-scaled by 1/8
__device__ float g_k[B_*H_*L_*D_];                 // 16 MB
__device__ float g_v[B_*H_*L_*D_];                 // 16 MB
__device__ float g_bias[(size_t)B_*H_*L_*L_];      // 256 MB  [B,H,L,L]
__device__ float g_attn[B_*L_*ND_];                // 16 MB   [B,L,H*D]

// ---------------------------------------------------------------------------
// tf32 mma.sync helpers
// ---------------------------------------------------------------------------
__device__ __forceinline__ uint32_t tf32r(float x) {
    uint32_t r;
    asm("cvt.rna.tf32.f32 %0, %1;" : "=r"(r) : "f"(x));
    return r;
}
__device__ __forceinline__ void split_tf32(float x, float& hi, float& lo) {
    uint32_t h = tf32r(x);
    hi = __uint_as_float(h);
    lo = __uint_as_float(tf32r(x - hi));
}
__device__ __forceinline__ void mma8(float* c,
                                     uint32_t a0, uint32_t a1, uint32_t a2, uint32_t a3,
                                     uint32_t b0, uint32_t b1) {
    asm volatile(
        "mma.sync.aligned.m16n8k8.row.col.f32.tf32.tf32.f32 "
        "{%0,%1,%2,%3}, {%4,%5,%6,%7}, {%8,%9}, {%0,%1,%2,%3};"
        : "+f"(c[0]), "+f"(c[1]), "+f"(c[2]), "+f"(c[3])
        : "r"(a0), "r"(a1), "r"(a2), "r"(a3), "r"(b0), "r"(b1));
}
__device__ __forceinline__ uint32_t fu(float x) { return __float_as_uint(x); }

// ---------------------------------------------------------------------------
// Kernel 1: QKV GEMM (tensor).  C[m,n]=dot(s[m,:],W[n,:]) M=4096,N=3072,K=1024
// 128x128 tile, BK=32, 256 thr, 8 warps (2x4), warp tile 64x32. 3xTF32 split.
// Scatter epilogue to g_q (x0.125) / g_k / g_v in [B,H,L,D].
// ---------------------------------------------------------------------------
#define GLD 36   // smem leading dim: 36 mod 32 = 4 -> conflict-free frag LDS
__global__ __launch_bounds__(256) void qkv_tc(const float* __restrict__ A,
                                              const float* __restrict__ W)
{
    extern __shared__ float sm[];
    float* Ah = sm;
    float* Al = Ah + 128*GLD;
    float* Bh = Al + 128*GLD;
    float* Bl = Bh + 128*GLD;
    const int K = ND_;
    int t = threadIdx.x, wid = t >> 5, lane = t & 31;
    int g = lane >> 2, tg = lane & 3;
    int m0 = blockIdx.y * 128, n0 = blockIdx.x * 128;
    int wm = wid >> 2, wn = wid & 3;

    float C[4][4][4];
#pragma unroll
    for (int i = 0; i < 4; ++i)
#pragma unroll
        for (int j = 0; j < 4; ++j) {
            C[i][j][0] = 0.f; C[i][j][1] = 0.f; C[i][j][2] = 0.f; C[i][j][3] = 0.f;
        }

    for (int kt = 0; kt < K; kt += 32) {
        __syncthreads();
#pragma unroll
        for (int i = t; i < 1024; i += 256) {
            int r = i >> 3, c = (i & 7) * 4;
            float4 av = *(const float4*)(A + (size_t)(m0 + r) * K + kt + c);
            float4 hv, lv;
            split_tf32(av.x, hv.x, lv.x); split_tf32(av.y, hv.y, lv.y);
            split_tf32(av.z, hv.z, lv.z); split_tf32(av.w, hv.w, lv.w);
            *(float4*)&Ah[r*GLD + c] = hv;
            *(float4*)&Al[r*GLD + c] = lv;
            float4 wv = *(const float4*)(W + (size_t)(n0 + r) * K + kt + c);
            split_tf32(wv.x, hv.x, lv.x); split_tf32(wv.y, hv.y, lv.y);
            split_tf32(wv.z, hv.z, lv.z); split_tf32(wv.w, hv.w, lv.w);
            *(float4*)&Bh[r*GLD + c] = hv;
            *(float4*)&Bl[r*GLD + c] = lv;
        }
        __syncthreads();
#pragma unroll
        for (int kk = 0; kk < 32; kk += 8) {
            uint32_t ah[4][4], al[4][4];
#pragma unroll
            for (int mt = 0; mt < 4; ++mt) {
                int ba = (wm*64 + mt*16 + g) * GLD + kk + tg;
                ah[mt][0] = fu(Ah[ba]);         ah[mt][1] = fu(Ah[ba + 8*GLD]);
                ah[mt][2] = fu(Ah[ba + 4]);     ah[mt][3] = fu(Ah[ba + 8*GLD + 4]);
                al[mt][0] = fu(Al[ba]);         al[mt][1] = fu(Al[ba + 8*GLD]);
                al[mt][2] = fu(Al[ba + 4]);     al[mt][3] = fu(Al[ba + 8*GLD + 4]);
            }
#pragma unroll
            for (int nt = 0; nt < 4; ++nt) {
                int bb = (wn*32 + nt*8 + g) * GLD + kk + tg;
                uint32_t bh0 = fu(Bh[bb]), bh1 = fu(Bh[bb + 4]);
                uint32_t bl0 = fu(Bl[bb]), bl1 = fu(Bl[bb + 4]);
#pragma unroll
                for (int mt = 0; mt < 4; ++mt) {
                    mma8(C[mt][nt], ah[mt][0], ah[mt][1], ah[mt][2], ah[mt][3], bh0, bh1);
                    mma8(C[mt][nt], ah[mt][0], ah[mt][1], ah[mt][2], ah[mt][3], bl0, bl1);
                    mma8(C[mt][nt], al[mt][0], al[mt][1], al[mt][2], al[mt][3], bh0, bh1);
                }
            }
        }
    }

#pragma unroll
    for (int mt = 0; mt < 4; ++mt) {
#pragma unroll
        for (int nt = 0; nt < 4; ++nt) {
            int m = m0 + wm*64 + mt*16 + g;
            int n = n0 + wn*32 + nt*8 + 2*tg;
            int part = n >> 10, rem = n & 1023;
            int h = rem >> 6, d = rem & 63;
            float sc = (part == 0) ? 0.125f : 1.0f;
            float* dst = (part == 0) ? g_q : ((part == 1) ? g_k : g_v);
            int bb0 = m >> 10, si0 = m & 1023;
            float* o0 = dst + ((size_t)(bb0*H_ + h) * L_ + si0) * D_ + d;
            float2 v0 = make_float2(C[mt][nt][0]*sc, C[mt][nt][1]*sc);
            *(float2*)o0 = v0;
            int m1 = m + 8;
            int bb1 = m1 >> 10, si1 = m1 & 1023;
            float* o1 = dst + ((size_t)(bb1*H_ + h) * L_ + si1) * D_ + d;
            float2 v1 = make_float2(C[mt][nt][2]*sc, C[mt][nt][3]*sc);
            *(float2*)o1 = v1;
        }
    }
}

// ---------------------------------------------------------------------------
// Kernel 2: pair bias (unchanged, memory-bound).
// ---------------------------------------------------------------------------
__global__ __launch_bounds__(256) void pairbias_kernel(const float* __restrict__ z,
                                                       const float* __restrict__ Wb,
                                                       const float* __restrict__ bb)
{
    __shared__ float zs[128 * 65];
    __shared__ float wbs[16 * 64];
    __shared__ float bbs[16];
    int t = threadIdx.x;
    size_t row0 = (size_t)blockIdx.x * 128;
    const float* zp = z + row0 * 64;

    for (int f = t; f < 2048; f += 256) {
        float4 v = *(const float4*)(zp + (size_t)f * 4);
        int r = f >> 4, c = (f & 15) * 4;
        zs[r*65+c] = v.x; zs[r*65+c+1] = v.y; zs[r*65+c+2] = v.z; zs[r*65+c+3] = v.w;
    }
    for (int i = t; i < 1024; i += 256) wbs[i] = Wb[i];
    if (t < 16) bbs[t] = bb[t];
    __syncthreads();

    int j  = t & 127;
    int hb = (t >> 7) * 8;

    float4 zr[16];
#pragma unroll
    for (int c4 = 0; c4 < 16; ++c4) {
        int c = c4 * 4;
        zr[c4] = make_float4(zs[j*65+c], zs[j*65+c+1], zs[j*65+c+2], zs[j*65+c+3]);
    }
    float acc[8];
#pragma unroll
    for (int hh = 0; hh < 8; ++hh) acc[hh] = bbs[hb + hh];
#pragma unroll
    for (int c4 = 0; c4 < 16; ++c4) {
        float4 zv = zr[c4];
#pragma unroll
        for (int hh = 0; hh < 8; ++hh) {
            float4 wv = *(const float4*)(wbs + (hb + hh) * 64 + c4 * 4);
            acc[hh] += zv.x*wv.x + zv.y*wv.y + zv.z*wv.z + zv.w*wv.w;
        }
    }

    size_t bi = row0 >> 10;
    int j0 = (int)(row0 & 1023);
    int bbatch = (int)(bi >> 10);
    int irow   = (int)(bi & 1023);
#pragma unroll
    for (int hh = 0; hh < 8; ++hh) {
        int h = hb + hh;
        g_bias[((size_t)(bbatch * H_ + h) * L_ + irow) * L_ + j0 + j] = acc[hh];
    }
}

// ---------------------------------------------------------------------------
// Kernel 3: flash attention on tensor cores, 3xTF32 for QK^T and PV.
// Block = (b, h, 128 q rows); 8 warps; each warp owns a 16-row q strip.
// kv tiles of 64. V consumed row-major (ld=72) — no transpose needed.
// ---------------------------------------------------------------------------
#define LQ 68   // 68 mod 32 = 4 -> conflict-free for g*ld+t frag pattern
#define LV 72   // 72 mod 32 = 8 -> conflict-free for t*ld+g frag pattern
__global__ __launch_bounds__(256) void attn_tc()
{
    extern __shared__ float sm[];
    float* Qh = sm;                  // 128*68
    float* Ql = Qh + 128*LQ;
    float* Kh = Ql + 128*LQ;         // 64*68
    float* Kl = Kh + 64*LQ;
    float* Vh = Kl + 64*LQ;          // 64*72
    float* Vl = Vh + 64*LV;
    float* Ph = Vl + 64*LV;          // 128*68 (bias staging, then P hi)
    float* Pl = Ph + 128*LQ;         // 128*68 (P lo)

    int t = threadIdx.x, wid = t >> 5, lane = t & 31;
    int g = lane >> 2, tg = lane & 3;
    int x = blockIdx.x;
    int qb = x & 7, h = (x >> 3) & 15, b = x >> 7;
    size_t bh = (size_t)b * H_ + h;
    int qw = wid * 16;               // warp's q-strip base within tile

    // load + split Q (128 x 64)
    const float* qp = g_q + (bh * L_ + (size_t)qb * 128) * D_;
    for (int i = t; i < 2048; i += 256) {
        int r = i >> 4, c = (i & 15) * 4;
        float4 v = *(const float4*)(qp + r * 64 + c);
        float4 hv, lv;
        split_tf32(v.x, hv.x, lv.x); split_tf32(v.y, hv.y, lv.y);
        split_tf32(v.z, hv.z, lv.z); split_tf32(v.w, hv.w, lv.w);
        *(float4*)&Qh[r*LQ + c] = hv;
        *(float4*)&Ql[r*LQ + c] = lv;
    }

    float O[8][4];
#pragma unroll
    for (int i = 0; i < 8; ++i) { O[i][0]=0.f; O[i][1]=0.f; O[i][2]=0.f; O[i][3]=0.f; }
    float mi0 = -1e30f, mi1 = -1e30f, li0 = 0.f, li1 = 0.f;

    const float* bp = g_bias + (bh * L_ + (size_t)qb * 128) * L_;

    for (int kb = 0; kb < 16; ++kb) {
        __syncthreads();   // prior iteration's PV reads done
        const float* kp = g_k + (bh * L_ + (size_t)kb * 64) * D_;
        const float* vp = g_v + (bh * L_ + (size_t)kb * 64) * D_;
        for (int i = t; i < 1024; i += 256) {
            int r = i >> 4, c = (i & 15) * 4;
            float4 kv = *(const float4*)(kp + r * 64 + c);
            float4 hv, lv;
            split_tf32(kv.x, hv.x, lv.x); split_tf32(kv.y, hv.y, lv.y);
            split_tf32(kv.z, hv.z, lv.z); split_tf32(kv.w, hv.w, lv.w);
            *(float4*)&Kh[r*LQ + c] = hv;
            *(float4*)&Kl[r*LQ + c] = lv;
            float4 vv = *(const float4*)(vp + r * 64 + c);
            split_tf32(vv.x, hv.x, lv.x); split_tf32(vv.y, hv.y, lv.y);
            split_tf32(vv.z, hv.z, lv.z); split_tf32(vv.w, hv.w, lv.w);
            *(float4*)&Vh[r*LV + c] = hv;
            *(float4*)&Vl[r*LV + c] = lv;
        }
        // stage bias tile (128 x 64) into Ph, coalesced
        for (int i = t; i < 2048; i += 256) {
            int r = i >> 4, c = (i & 15) * 4;
            float4 bv = *(const float4*)(bp + (size_t)r * L_ + kb * 64 + c);
            *(float4*)&Ph[r*LQ + c] = bv;
        }
        __syncthreads();

        // S = Q K^T  (16 x 64 per warp)
        float S[8][4];
#pragma unroll
        for (int i = 0; i < 8; ++i) { S[i][0]=0.f; S[i][1]=0.f; S[i][2]=0.f; S[i][3]=0.f; }
#pragma unroll
        for (int kk = 0; kk < 64; kk += 8) {
            int qa = (qw + g) * LQ + kk + tg;
            uint32_t ah0 = fu(Qh[qa]),     ah1 = fu(Qh[qa + 8*LQ]);
            uint32_t ah2 = fu(Qh[qa + 4]), ah3 = fu(Qh[qa + 8*LQ + 4]);
            uint32_t al0 = fu(Ql[qa]),     al1 = fu(Ql[qa + 8*LQ]);
            uint32_t al2 = fu(Ql[qa + 4]), al3 = fu(Ql[qa + 8*LQ + 4]);
#pragma unroll
            for (int nt = 0; nt < 8; ++nt) {
                int ka = (nt*8 + g) * LQ + kk + tg;
                uint32_t bh0 = fu(Kh[ka]), bh1 = fu(Kh[ka + 4]);
                uint32_t bl0 = fu(Kl[ka]), bl1 = fu(Kl[ka + 4]);
                mma8(S[nt], ah0, ah1, ah2, ah3, bh0, bh1);
                mma8(S[nt], ah0, ah1, ah2, ah3, bl0, bl1);
                mma8(S[nt], al0, al1, al2, al3, bh0, bh1);
            }
        }

        // bias add + online softmax (thread owns rows qw+g and qw+g+8)
        float rm0 = -1e30f, rm1 = -1e30f;
#pragma unroll
        for (int nt = 0; nt < 8; ++nt) {
            float2 b0 = *(const float2*)&Ph[(qw + g) * LQ + nt*8 + 2*tg];
            float2 b1 = *(const float2*)&Ph[(qw + g + 8) * LQ + nt*8 + 2*tg];
            S[nt][0] += b0.x; S[nt][1] += b0.y;
            S[nt][2] += b1.x; S[nt][3] += b1.y;
            rm0 = fmaxf(rm0, fmaxf(S[nt][0], S[nt][1]));
            rm1 = fmaxf(rm1, fmaxf(S[nt][2], S[nt][3]));
        }
        rm0 = fmaxf(rm0, __shfl_xor_sync(0xffffffffu, rm0, 1));
        rm0 = fmaxf(rm0, __shfl_xor_sync(0xffffffffu, rm0, 2));
        rm1 = fmaxf(rm1, __shfl_xor_sync(0xffffffffu, rm1, 1));
        rm1 = fmaxf(rm1, __shfl_xor_sync(0xffffffffu, rm1, 2));
        float nm0 = fmaxf(mi0, rm0), nm1 = fmaxf(mi1, rm1);
        float cr0 = __expf(mi0 - nm0), cr1 = __expf(mi1 - nm1);
        float rs0 = 0.f, rs1 = 0.f;
#pragma unroll
        for (int nt = 0; nt < 8; ++nt) {
            S[nt][0] = __expf(S[nt][0] - nm0);
            S[nt][1] = __expf(S[nt][1] - nm0);
            S[nt][2] = __expf(S[nt][2] - nm1);
            S[nt][3] = __expf(S[nt][3] - nm1);
            rs0 += S[nt][0] + S[nt][1];
            rs1 += S[nt][2] + S[nt][3];
        }
        rs0 += __shfl_xor_sync(0xffffffffu, rs0, 1);
        rs0 += __shfl_xor_sync(0xffffffffu, rs0, 2);
        rs1 += __shfl_xor_sync(0xffffffffu, rs1, 1);
        rs1 += __shfl_xor_sync(0xffffffffu, rs1, 2);
        li0 = li0 * cr0 + rs0;  mi0 = nm0;
        li1 = li1 * cr1 + rs1;  mi1 = nm1;
#pragma unroll
        for (int nt = 0; nt < 8; ++nt) {
            O[nt][0] *= cr0; O[nt][1] *= cr0;
            O[nt][2] *= cr1; O[nt][3] *= cr1;
        }
        // write P split (same elements this thread owns -> no cross-thread hazard)
#pragma unroll
        for (int nt = 0; nt < 8; ++nt) {
            float h0, l0, h1, l1;
            split_tf32(S[nt][0], h0, l0); split_tf32(S[nt][1], h1, l1);
            *(float2*)&Ph[(qw + g) * LQ + nt*8 + 2*tg] = make_float2(h0, h1);
            *(float2*)&Pl[(qw + g) * LQ + nt*8 + 2*tg] = make_float2(l0, l1);
            split_tf32(S[nt][2], h0, l0); split_tf32(S[nt][3], h1, l1);
            *(float2*)&Ph[(qw + g + 8) * LQ + nt*8 + 2*tg] = make_float2(h0, h1);
            *(float2*)&Pl[(qw + g + 8) * LQ + nt*8 + 2*tg] = make_float2(l0, l1);
        }
        __syncwarp();   // warp reads only its own strip of P

        // O += P V  (keys are the k-dim)
#pragma unroll
        for (int kk = 0; kk < 64; kk += 8) {
            int pa = (qw + g) * LQ + kk + tg;
            uint32_t ah0 = fu(Ph[pa]),     ah1 = fu(Ph[pa + 8*LQ]);
            uint32_t ah2 = fu(Ph[pa + 4]), ah3 = fu(Ph[pa + 8*LQ + 4]);
            uint32_t al0 = fu(Pl[pa]),     al1 = fu(Pl[pa + 8*LQ]);
            uint32_t al2 = fu(Pl[pa + 4]), al3 = fu(Pl[pa + 8*LQ + 4]);
#pragma unroll
            for (int nt = 0; nt < 8; ++nt) {
                int va = (kk + tg) * LV + nt*8 + g;
                uint32_t bh0 = fu(Vh[va]), bh1 = fu(Vh[va + 4*LV]);
                uint32_t bl0 = fu(Vl[va]), bl1 = fu(Vl[va + 4*LV]);
                mma8(O[nt], ah0, ah1, ah2, ah3, bh0, bh1);
                mma8(O[nt], ah0, ah1, ah2, ah3, bl0, bl1);
                mma8(O[nt], al0, al1, al2, al3, bh0, bh1);
            }
        }
    }

    float inv0 = 1.0f / li0, inv1 = 1.0f / li1;
    int q0 = qb * 128 + qw + g;
    float* ob = g_attn + ((size_t)b * L_ + q0) * ND_ + h * D_;
#pragma unroll
    for (int nt = 0; nt < 8; ++nt) {
        *(float2*)(ob + nt*8 + 2*tg) =
            make_float2(O[nt][0]*inv0, O[nt][1]*inv0);
        *(float2*)(ob + (size_t)8 * ND_ + nt*8 + 2*tg) =
            make_float2(O[nt][2]*inv1, O[nt][3]*inv1);
    }
}

// ---------------------------------------------------------------------------
// Kernel 4: output projection (tensor).  M=4096, N=1024, K=1024. 3xTF32.
// ---------------------------------------------------------------------------
__global__ __launch_bounds__(256) void proj_tc(const float* __restrict__ Wout,
                                               const float* __restrict__ bout,
                                               float* __restrict__ out)
{
    extern __shared__ float sm[];
    float* Ah = sm;
    float* Al = Ah + 128*GLD;
    float* Bh = Al + 128*GLD;
    float* Bl = Bh + 128*GLD;
    const float* A = g_attn;
    const int K = ND_;
    int t = threadIdx.x, wid = t >> 5, lane = t & 31;
    int g = lane >> 2, tg = lane & 3;
    int m0 = blockIdx.y * 128, n0 = blockIdx.x * 128;
    int wm = wid >> 2, wn = wid & 3;

    float C[4][4][4];
#pragma unroll
    for (int i = 0; i < 4; ++i)
#pragma unroll
        for (int j = 0; j < 4; ++j) {
            C[i][j][0] = 0.f; C[i][j][1] = 0.f; C[i][j][2] = 0.f; C[i][j][3] = 0.f;
        }

    for (int kt = 0; kt < K; kt += 32) {
        __syncthreads();
#pragma unroll
        for (int i = t; i < 1024; i += 256) {
            int r = i >> 3, c = (i & 7) * 4;
            float4 av = *(const float4*)(A + (size_t)(m0 + r) * K + kt + c);
            float4 hv, lv;
            split_tf32(av.x, hv.x, lv.x); split_tf32(av.y, hv.y, lv.y);
            split_tf32(av.z, hv.z, lv.z); split_tf32(av.w, hv.w, lv.w);
            *(float4*)&Ah[r*GLD + c] = hv;
            *(float4*)&Al[r*GLD + c] = lv;
            float4 wv = *(const float4*)(Wout + (size_t)(n0 + r) * K + kt + c);
            split_tf32(wv.x, hv.x, lv.x); split_tf32(wv.y, hv.y, lv.y);
            split_tf32(wv.z, hv.z, lv.z); split_tf32(wv.w, hv.w, lv.w);
            *(float4*)&Bh[r*GLD + c] = hv;
            *(float4*)&Bl[r*GLD + c] = lv;
        }
        __syncthreads();
#pragma unroll
        for (int kk = 0; kk < 32; kk += 8) {
            uint32_t ah[4][4], al[4][4];
#pragma unroll
            for (int mt = 0; mt < 4; ++mt) {
                int ba = (wm*64 + mt*16 + g) * GLD + kk + tg;
                ah[mt][0] = fu(Ah[ba]);         ah[mt][1] = fu(Ah[ba + 8*GLD]);
                ah[mt][2] = fu(Ah[ba + 4]);     ah[mt][3] = fu(Ah[ba + 8*GLD + 4]);
                al[mt][0] = fu(Al[ba]);         al[mt][1] = fu(Al[ba + 8*GLD]);
                al[mt][2] = fu(Al[ba + 4]);     al[mt][3] = fu(Al[ba + 8*GLD + 4]);
            }
#pragma unroll
            for (int nt = 0; nt < 4; ++nt) {
                int bb = (wn*32 + nt*8 + g) * GLD + kk + tg;
                uint32_t bh0 = fu(Bh[bb]), bh1 = fu(Bh[bb + 4]);
                uint32_t bl0 = fu(Bl[bb]), bl1 = fu(Bl[bb + 4]);
#pragma unroll
                for (int mt = 0; mt < 4; ++mt) {
                    mma8(C[mt][nt], ah[mt][0], ah[mt][1], ah[mt][2], ah[mt][3], bh0, bh1);
                    mma8(C[mt][nt], ah[mt][0], ah[mt][1], ah[mt][2], ah[mt][3], bl0, bl1);
                    mma8(C[mt][nt], al[mt][0], al[mt][1], al[mt][2], al[mt][3], bh0, bh1);
                }
            }
        }
    }

#pragma unroll
    for (int mt = 0; mt < 4; ++mt) {
#pragma unroll
        for (int nt = 0; nt < 4; ++nt) {
            int m = m0 + wm*64 + mt*16 + g;
            int n = n0 + wn*32 + nt*8 + 2*tg;
            float2 bo = *(const float2*)(bout + n);
            *(float2*)(out + (size_t)m * ND_ + n) =
                make_float2(C[mt][nt][0] + bo.x, C[mt][nt][1] + bo.y);
            *(float2*)(out + (size_t)(m + 8) * ND_ + n) =
                make_float2(C[mt][nt][2] + bo.x, C[mt][nt][3] + bo.y);
        }
    }
}

// ---------------------------------------------------------------------------
extern "C" void kernel_launch(void* const* d_in, const int* in_sizes, int n_in,
                              void* d_out, int out_size)
{
    const float* s      = (const float*)d_in[0];
    const float* z      = (const float*)d_in[1];
    const float* W_qkv  = (const float*)d_in[2];
    const float* W_bias = (const float*)d_in[3];
    const float* b_bias = (const float*)d_in[4];
    const float* W_out  = (const float*)d_in[5];
    const float* b_out  = (const float*)d_in[6];
    float* out = (float*)d_out;

    (void)in_sizes; (void)n_in; (void)out_size;

    const int gemm_smem = 128 * GLD * 4 * sizeof(float);          // 73728
    const int attn_smem = (2*128*LQ + 2*64*LQ + 2*64*LV + 2*128*LQ) * sizeof(float); // 210944

    cudaFuncSetAttribute(qkv_tc,  cudaFuncAttributeMaxDynamicSharedMemorySize, gemm_smem);
    cudaFuncSetAttribute(proj_tc, cudaFuncAttributeMaxDynamicSharedMemorySize, gemm_smem);
    cudaFuncSetAttribute(attn_tc, cudaFuncAttributeMaxDynamicSharedMemorySize, attn_smem);

    dim3 g1(24, 32);
    qkv_tc<<<g1, 256, gemm_smem>>>(s, W_qkv);

    pairbias_kernel<<<32768, 256>>>(z, W_bias, b_bias);

    attn_tc<<<512, 256, attn_smem>>>();

    dim3 g4(8, 32);
    proj_tc<<<g4, 256, gemm_smem>>>(W_out, b_out, out);
}

// round 4
// speedup vs baseline: 1.1634x; 1.0417x over previous
#include <cuda_runtime.h>
#include <stdint.h>

#define B_  4
#define L_  1024
#define H_  16
#define D_  64
#define ND_ 1024

// Scratch (allocation-free rule: __device__ globals)
__device__ float g_q[B_*H_*L_*D_];                 // 16 MB, pre-scaled by 1/8
__device__ float g_k[B_*H_*L_*D_];                 // 16 MB
__device__ float g_v[B_*H_*L_*D_];                 // 16 MB
__device__ float g_bias[(size_t)B_*H_*L_*L_];      // 256 MB  [B,H,L,L]
__device__ float g_attn[B_*L_*ND_];                // 16 MB   [B,L,H*D]

// ---------------------------------------------------------------------------
// tf32 mma.sync helpers
// ---------------------------------------------------------------------------
__device__ __forceinline__ uint32_t tf32r(float x) {
    uint32_t r;
    asm("cvt.rna.tf32.f32 %0, %1;" : "=r"(r) : "f"(x));
    return r;
}
// split fp32 -> (hi, lo) tf32 bit patterns, in registers
__device__ __forceinline__ void split_u(float x, uint32_t& h, uint32_t& l) {
    uint32_t hb = tf32r(x);
    float hf = __uint_as_float(hb);
    h = hb;
    l = tf32r(x - hf);
}
__device__ __forceinline__ void mma8(float* c,
                                     uint32_t a0, uint32_t a1, uint32_t a2, uint32_t a3,
                                     uint32_t b0, uint32_t b1) {
    asm volatile(
        "mma.sync.aligned.m16n8k8.row.col.f32.tf32.tf32.f32 "
        "{%0,%1,%2,%3}, {%4,%5,%6,%7}, {%8,%9}, {%0,%1,%2,%3};"
        : "+f"(c[0]), "+f"(c[1]), "+f"(c[2]), "+f"(c[3])
        : "r"(a0), "r"(a1), "r"(a2), "r"(a3), "r"(b0), "r"(b1));
}
__device__ __forceinline__ void cp16(void* dst, const void* src) {
    uint32_t d = (uint32_t)__cvta_generic_to_shared(dst);
    asm volatile("cp.async.cg.shared.global [%0], [%1], 16;" :: "r"(d), "l"(src));
}
#define CP_COMMIT() asm volatile("cp.async.commit_group;")
#define CP_WAIT(n)  asm volatile("cp.async.wait_group %0;" :: "n"(n))

// ---------------------------------------------------------------------------
// Shared GEMM core: 128x128 tile, BK=32, 8 warps (2x4), warp tile 64x32.
// fp32 in smem (cp.async, 2-stage double buffer), 3xTF32 split at frag load.
// ---------------------------------------------------------------------------
#define GLD 36   // 36 mod 32 = 4 -> conflict-free frag LDS

struct Frag { uint32_t h[4], l[4]; };

__device__ __forceinline__ void gemm_core(const float* __restrict__ A,
                                          const float* __restrict__ Wm,
                                          int m0, int n0, int K,
                                          float* smem, float C[4][4][4])
{
    float* As[2] = { smem,               smem + 128*GLD };
    float* Bs[2] = { smem + 2*128*GLD,   smem + 3*128*GLD };
    int t = threadIdx.x, wid = t >> 5, lane = t & 31;
    int g = lane >> 2, tg = lane & 3;
    int wm = wid >> 2, wn = wid & 3;

#pragma unroll
    for (int i = 0; i < 4; ++i)
#pragma unroll
        for (int j = 0; j < 4; ++j) {
            C[i][j][0] = 0.f; C[i][j][1] = 0.f; C[i][j][2] = 0.f; C[i][j][3] = 0.f;
        }

    const int NS = K / 32;
    // stage 0 preload
    {
#pragma unroll
        for (int i = t; i < 1024; i += 256) {
            int r = i >> 3, c = (i & 7) * 4;
            cp16(&As[0][r*GLD + c], A  + (size_t)(m0 + r) * K + c);
            cp16(&Bs[0][r*GLD + c], Wm + (size_t)(n0 + r) * K + c);
        }
        CP_COMMIT();
    }

    for (int s = 0; s < NS; ++s) {
        if (s + 1 < NS) {
            int kt = (s + 1) * 32, p = (s + 1) & 1;
#pragma unroll
            for (int i = t; i < 1024; i += 256) {
                int r = i >> 3, c = (i & 7) * 4;
                cp16(&As[p][r*GLD + c], A  + (size_t)(m0 + r) * K + kt + c);
                cp16(&Bs[p][r*GLD + c], Wm + (size_t)(n0 + r) * K + kt + c);
            }
            CP_COMMIT();
            CP_WAIT(1);
        } else {
            CP_WAIT(0);
        }
        __syncthreads();

        int p = s & 1;
        const float* Ap = As[p];
        const float* Bp = Bs[p];
#pragma unroll
        for (int kk = 0; kk < 32; kk += 8) {
            Frag af[4];
#pragma unroll
            for (int mt = 0; mt < 4; ++mt) {
                int ba = (wm*64 + mt*16 + g) * GLD + kk + tg;
                split_u(Ap[ba],            af[mt].h[0], af[mt].l[0]);
                split_u(Ap[ba + 8*GLD],    af[mt].h[1], af[mt].l[1]);
                split_u(Ap[ba + 4],        af[mt].h[2], af[mt].l[2]);
                split_u(Ap[ba + 8*GLD+4],  af[mt].h[3], af[mt].l[3]);
            }
#pragma unroll
            for (int nt = 0; nt < 4; ++nt) {
                int bb = (wn*32 + nt*8 + g) * GLD + kk + tg;
                uint32_t bh0, bl0, bh1, bl1;
                split_u(Bp[bb],     bh0, bl0);
                split_u(Bp[bb + 4], bh1, bl1);
#pragma unroll
                for (int mt = 0; mt < 4; ++mt) {
                    mma8(C[mt][nt], af[mt].h[0], af[mt].h[1], af[mt].h[2], af[mt].h[3], bh0, bh1);
                    mma8(C[mt][nt], af[mt].h[0], af[mt].h[1], af[mt].h[2], af[mt].h[3], bl0, bl1);
                    mma8(C[mt][nt], af[mt].l[0], af[mt].l[1], af[mt].l[2], af[mt].l[3], bh0, bh1);
                }
            }
        }
        __syncthreads();
    }
}

// ---------------------------------------------------------------------------
// Kernel 1: QKV GEMM.  M=4096, N=3072, K=1024. Scatter to q(x0.125)/k/v.
// ---------------------------------------------------------------------------
__global__ __launch_bounds__(256) void qkv_tc(const float* __restrict__ A,
                                              const float* __restrict__ W)
{
    extern __shared__ float sm[];
    int t = threadIdx.x, wid = t >> 5, lane = t & 31;
    int g = lane >> 2, tg = lane & 3;
    int m0 = blockIdx.y * 128, n0 = blockIdx.x * 128;
    int wm = wid >> 2, wn = wid & 3;

    float C[4][4][4];
    gemm_core(A, W, m0, n0, ND_, sm, C);

#pragma unroll
    for (int mt = 0; mt < 4; ++mt) {
#pragma unroll
        for (int nt = 0; nt < 4; ++nt) {
            int m = m0 + wm*64 + mt*16 + g;
            int n = n0 + wn*32 + nt*8 + 2*tg;
            int part = n >> 10, rem = n & 1023;
            int h = rem >> 6, d = rem & 63;
            float sc = (part == 0) ? 0.125f : 1.0f;
            float* dst = (part == 0) ? g_q : ((part == 1) ? g_k : g_v);
            int bb0 = m >> 10, si0 = m & 1023;
            float* o0 = dst + ((size_t)(bb0*H_ + h) * L_ + si0) * D_ + d;
            *(float2*)o0 = make_float2(C[mt][nt][0]*sc, C[mt][nt][1]*sc);
            int m1 = m + 8;
            int bb1 = m1 >> 10, si1 = m1 & 1023;
            float* o1 = dst + ((size_t)(bb1*H_ + h) * L_ + si1) * D_ + d;
            *(float2*)o1 = make_float2(C[mt][nt][2]*sc, C[mt][nt][3]*sc);
        }
    }
}

// ---------------------------------------------------------------------------
// Kernel 4: output projection.  M=4096, N=1024, K=1024.
// ---------------------------------------------------------------------------
__global__ __launch_bounds__(256) void proj_tc(const float* __restrict__ Wout,
                                               const float* __restrict__ bout,
                                               float* __restrict__ out)
{
    extern __shared__ float sm[];
    int t = threadIdx.x, wid = t >> 5, lane = t & 31;
    int g = lane >> 2, tg = lane & 3;
    int m0 = blockIdx.y * 128, n0 = blockIdx.x * 128;
    int wm = wid >> 2, wn = wid & 3;

    float C[4][4][4];
    gemm_core(g_attn, Wout, m0, n0, ND_, sm, C);

#pragma unroll
    for (int mt = 0; mt < 4; ++mt) {
#pragma unroll
        for (int nt = 0; nt < 4; ++nt) {
            int m = m0 + wm*64 + mt*16 + g;
            int n = n0 + wn*32 + nt*8 + 2*tg;
            float2 bo = *(const float2*)(bout + n);
            *(float2*)(out + (size_t)m * ND_ + n) =
                make_float2(C[mt][nt][0] + bo.x, C[mt][nt][1] + bo.y);
            *(float2*)(out + (size_t)(m + 8) * ND_ + n) =
                make_float2(C[mt][nt][2] + bo.x, C[mt][nt][3] + bo.y);
        }
    }
}

// ---------------------------------------------------------------------------
// Kernel 2: pair bias (memory-bound, unchanged).
// ---------------------------------------------------------------------------
__global__ __launch_bounds__(256) void pairbias_kernel(const float* __restrict__ z,
                                                       const float* __restrict__ Wb,
                                                       const float* __restrict__ bb)
{
    __shared__ float zs[128 * 65];
    __shared__ float wbs[16 * 64];
    __shared__ float bbs[16];
    int t = threadIdx.x;
    size_t row0 = (size_t)blockIdx.x * 128;
    const float* zp = z + row0 * 64;

    for (int f = t; f < 2048; f += 256) {
        float4 v = *(const float4*)(zp + (size_t)f * 4);
        int r = f >> 4, c = (f & 15) * 4;
        zs[r*65+c] = v.x; zs[r*65+c+1] = v.y; zs[r*65+c+2] = v.z; zs[r*65+c+3] = v.w;
    }
    for (int i = t; i < 1024; i += 256) wbs[i] = Wb[i];
    if (t < 16) bbs[t] = bb[t];
    __syncthreads();

    int j  = t & 127;
    int hb = (t >> 7) * 8;

    float4 zr[16];
#pragma unroll
    for (int c4 = 0; c4 < 16; ++c4) {
        int c = c4 * 4;
        zr[c4] = make_float4(zs[j*65+c], zs[j*65+c+1], zs[j*65+c+2], zs[j*65+c+3]);
    }
    float acc[8];
#pragma unroll
    for (int hh = 0; hh < 8; ++hh) acc[hh] = bbs[hb + hh];
#pragma unroll
    for (int c4 = 0; c4 < 16; ++c4) {
        float4 zv = zr[c4];
#pragma unroll
        for (int hh = 0; hh < 8; ++hh) {
            float4 wv = *(const float4*)(wbs + (hb + hh) * 64 + c4 * 4);
            acc[hh] += zv.x*wv.x + zv.y*wv.y + zv.z*wv.z + zv.w*wv.w;
        }
    }

    size_t bi = row0 >> 10;
    int j0 = (int)(row0 & 1023);
    int bbatch = (int)(bi >> 10);
    int irow   = (int)(bi & 1023);
#pragma unroll
    for (int hh = 0; hh < 8; ++hh) {
        int h = hb + hh;
        g_bias[((size_t)(bbatch * H_ + h) * L_ + irow) * L_ + j0 + j] = acc[hh];
    }
}

// ---------------------------------------------------------------------------
// Kernel 3: flash attention on tensor cores, fp32 smem + reg-time 3xTF32 split.
// Block = (b, h, 128 q rows); 8 warps, warp owns 16-row strip; kv tiles of 64.
// smem ~103 KB -> 2 CTAs/SM.
// ---------------------------------------------------------------------------
#define LQ 68   // 68 mod 32 = 4 -> conflict-free for (g*ld + tg) frag pattern
#define LV 72   // 72 mod 32 = 8 -> conflict-free for (tg*ld + g) frag pattern
__global__ __launch_bounds__(256, 2) void attn_tc()
{
    extern __shared__ float sm[];
    float* Qs = sm;                 // 128*68
    float* Ks = Qs + 128*LQ;        // 64*68
    float* Vs = Ks + 64*LQ;         // 64*72
    float* Ps = Vs + 64*LV;         // 128*68 (bias staging, then P)

    int t = threadIdx.x, wid = t >> 5, lane = t & 31;
    int g = lane >> 2, tg = lane & 3;
    int x = blockIdx.x;
    int qb = x & 7, h = (x >> 3) & 15, b = x >> 7;
    size_t bh = (size_t)b * H_ + h;
    int qw = wid * 16;

    const float* qp = g_q + (bh * L_ + (size_t)qb * 128) * D_;
    for (int i = t; i < 2048; i += 256) {
        int r = i >> 4, c = (i & 15) * 4;
        *(float4*)&Qs[r*LQ + c] = *(const float4*)(qp + r * 64 + c);
    }

    float O[8][4];
#pragma unroll
    for (int i = 0; i < 8; ++i) { O[i][0]=0.f; O[i][1]=0.f; O[i][2]=0.f; O[i][3]=0.f; }
    float mi0 = -1e30f, mi1 = -1e30f, li0 = 0.f, li1 = 0.f;

    const float* bp = g_bias + (bh * L_ + (size_t)qb * 128) * L_;

    for (int kb = 0; kb < 16; ++kb) {
        __syncthreads();   // prior PV reads of Ks/Vs/Ps complete
        const float* kp = g_k + (bh * L_ + (size_t)kb * 64) * D_;
        const float* vp = g_v + (bh * L_ + (size_t)kb * 64) * D_;
        for (int i = t; i < 1024; i += 256) {
            int r = i >> 4, c = (i & 15) * 4;
            *(float4*)&Ks[r*LQ + c] = *(const float4*)(kp + r * 64 + c);
            *(float4*)&Vs[r*LV + c] = *(const float4*)(vp + r * 64 + c);
        }
        for (int i = t; i < 2048; i += 256) {
            int r = i >> 4, c = (i & 15) * 4;
            *(float4*)&Ps[r*LQ + c] = *(const float4*)(bp + (size_t)r * L_ + kb * 64 + c);
        }
        __syncthreads();

        // S = Q K^T (16 x 64 per warp), 3xTF32
        float S[8][4];
#pragma unroll
        for (int i = 0; i < 8; ++i) { S[i][0]=0.f; S[i][1]=0.f; S[i][2]=0.f; S[i][3]=0.f; }
#pragma unroll
        for (int kk = 0; kk < 64; kk += 8) {
            int qa = (qw + g) * LQ + kk + tg;
            uint32_t ah0,al0,ah1,al1,ah2,al2,ah3,al3;
            split_u(Qs[qa],           ah0, al0);
            split_u(Qs[qa + 8*LQ],    ah1, al1);
            split_u(Qs[qa + 4],       ah2, al2);
            split_u(Qs[qa + 8*LQ+4],  ah3, al3);
#pragma unroll
            for (int nt = 0; nt < 8; ++nt) {
                int ka = (nt*8 + g) * LQ + kk + tg;
                uint32_t bh0, bl0, bh1, bl1;
                split_u(Ks[ka],     bh0, bl0);
                split_u(Ks[ka + 4], bh1, bl1);
                mma8(S[nt], ah0, ah1, ah2, ah3, bh0, bh1);
                mma8(S[nt], ah0, ah1, ah2, ah3, bl0, bl1);
                mma8(S[nt], al0, al1, al2, al3, bh0, bh1);
            }
        }

        // bias add + online softmax (thread owns rows qw+g, qw+g+8)
        float rm0 = -1e30f, rm1 = -1e30f;
#pragma unroll
        for (int nt = 0; nt < 8; ++nt) {
            float2 b0 = *(const float2*)&Ps[(qw + g) * LQ + nt*8 + 2*tg];
            float2 b1 = *(const float2*)&Ps[(qw + g + 8) * LQ + nt*8 + 2*tg];
            S[nt][0] += b0.x; S[nt][1] += b0.y;
            S[nt][2] += b1.x; S[nt][3] += b1.y;
            rm0 = fmaxf(rm0, fmaxf(S[nt][0], S[nt][1]));
            rm1 = fmaxf(rm1, fmaxf(S[nt][2], S[nt][3]));
        }
        rm0 = fmaxf(rm0, __shfl_xor_sync(0xffffffffu, rm0, 1));
        rm0 = fmaxf(rm0, __shfl_xor_sync(0xffffffffu, rm0, 2));
        rm1 = fmaxf(rm1, __shfl_xor_sync(0xffffffffu, rm1, 1));
        rm1 = fmaxf(rm1, __shfl_xor_sync(0xffffffffu, rm1, 2));
        float nm0 = fmaxf(mi0, rm0), nm1 = fmaxf(mi1, rm1);
        float cr0 = __expf(mi0 - nm0), cr1 = __expf(mi1 - nm1);
        float rs0 = 0.f, rs1 = 0.f;
#pragma unroll
        for (int nt = 0; nt < 8; ++nt) {
            S[nt][0] = __expf(S[nt][0] - nm0);
            S[nt][1] = __expf(S[nt][1] - nm0);
            S[nt][2] = __expf(S[nt][2] - nm1);
            S[nt][3] = __expf(S[nt][3] - nm1);
            rs0 += S[nt][0] + S[nt][1];
            rs1 += S[nt][2] + S[nt][3];
        }
        rs0 += __shfl_xor_sync(0xffffffffu, rs0, 1);
        rs0 += __shfl_xor_sync(0xffffffffu, rs0, 2);
        rs1 += __shfl_xor_sync(0xffffffffu, rs1, 1);
        rs1 += __shfl_xor_sync(0xffffffffu, rs1, 2);
        li0 = li0 * cr0 + rs0;  mi0 = nm0;
        li1 = li1 * cr1 + rs1;  mi1 = nm1;
#pragma unroll
        for (int nt = 0; nt < 8; ++nt) {
            O[nt][0] *= cr0; O[nt][1] *= cr0;
            O[nt][2] *= cr1; O[nt][3] *= cr1;
        }
        // write P (fp32) over the bias staging area (same thread-owned slots)
#pragma unroll
        for (int nt = 0; nt < 8; ++nt) {
            *(float2*)&Ps[(qw + g) * LQ + nt*8 + 2*tg]     = make_float2(S[nt][0], S[nt][1]);
            *(float2*)&Ps[(qw + g + 8) * LQ + nt*8 + 2*tg] = make_float2(S[nt][2], S[nt][3]);
        }
        __syncwarp();   // warp reads only its own strip of P

        // O += P V
#pragma unroll
        for (int kk = 0; kk < 64; kk += 8) {
            int pa = (qw + g) * LQ + kk + tg;
            uint32_t ah0,al0,ah1,al1,ah2,al2,ah3,al3;
            split_u(Ps[pa],           ah0, al0);
            split_u(Ps[pa + 8*LQ],    ah1, al1);
            split_u(Ps[pa + 4],       ah2, al2);
            split_u(Ps[pa + 8*LQ+4],  ah3, al3);
#pragma unroll
            for (int nt = 0; nt < 8; ++nt) {
                int va = (kk + tg) * LV + nt*8 + g;
                uint32_t bh0, bl0, bh1, bl1;
                split_u(Vs[va],          bh0, bl0);
                split_u(Vs[va + 4*LV],   bh1, bl1);
                mma8(O[nt], ah0, ah1, ah2, ah3, bh0, bh1);
                mma8(O[nt], ah0, ah1, ah2, ah3, bl0, bl1);
                mma8(O[nt], al0, al1, al2, al3, bh0, bh1);
            }
        }
    }

    float inv0 = 1.0f / li0, inv1 = 1.0f / li1;
    int q0 = qb * 128 + qw + g;
    float* ob = g_attn + ((size_t)b * L_ + q0) * ND_ + h * D_;
#pragma unroll
    for (int nt = 0; nt < 8; ++nt) {
        *(float2*)(ob + nt*8 + 2*tg) =
            make_float2(O[nt][0]*inv0, O[nt][1]*inv0);
        *(float2*)(ob + (size_t)8 * ND_ + nt*8 + 2*tg) =
            make_float2(O[nt][2]*inv1, O[nt][3]*inv1);
    }
}

// ---------------------------------------------------------------------------
extern "C" void kernel_launch(void* const* d_in, const int* in_sizes, int n_in,
                              void* d_out, int out_size)
{
    const float* s      = (const float*)d_in[0];
    const float* z      = (const float*)d_in[1];
    const float* W_qkv  = (const float*)d_in[2];
    const float* W_bias = (const float*)d_in[3];
    const float* b_bias = (const float*)d_in[4];
    const float* W_out  = (const float*)d_in[5];
    const float* b_out  = (const float*)d_in[6];
    float* out = (float*)d_out;

    (void)in_sizes; (void)n_in; (void)out_size;

    const int gemm_smem = 4 * 128 * GLD * sizeof(float);                       // 73728
    const int attn_smem = (128*LQ + 64*LQ + 64*LV + 128*LQ) * sizeof(float);   // 105472

    cudaFuncSetAttribute(qkv_tc,  cudaFuncAttributeMaxDynamicSharedMemorySize, gemm_smem);
    cudaFuncSetAttribute(proj_tc, cudaFuncAttributeMaxDynamicSharedMemorySize, gemm_smem);
    cudaFuncSetAttribute(attn_tc, cudaFuncAttributeMaxDynamicSharedMemorySize, attn_smem);

    dim3 g1(24, 32);
    qkv_tc<<<g1, 256, gemm_smem>>>(s, W_qkv);

    pairbias_kernel<<<32768, 256>>>(z, W_bias, b_bias);

    attn_tc<<<512, 256, attn_smem>>>();

    dim3 g4(8, 32);
    proj_tc<<<g4, 256, gemm_smem>>>(W_out, b_out, out);
}

// round 5
// speedup vs baseline: 1.2977x; 1.1155x over previous
#include <cuda_runtime.h>
#include <stdint.h>

#define B_  4
#define L_  1024
#define H_  16
#define D_  64
#define ND_ 1024

// Scratch (allocation-free rule: __device__ globals)
__device__ float g_q[B_*H_*L_*D_];                 // 16 MB, pre-scaled by 1/8
__device__ float g_k[B_*H_*L_*D_];                 // 16 MB
__device__ float g_v[B_*H_*L_*D_];                 // 16 MB
__device__ float g_bias[(size_t)B_*H_*L_*L_];      // 256 MB  [B,H,L,L]
__device__ float g_attn[B_*L_*ND_];                // 16 MB   [B,L,H*D]

// ---------------------------------------------------------------------------
// tf32 mma.sync helpers
// ---------------------------------------------------------------------------
__device__ __forceinline__ uint32_t tf32r(float x) {
    uint32_t r;
    asm("cvt.rna.tf32.f32 %0, %1;" : "=r"(r) : "f"(x));
    return r;
}
__device__ __forceinline__ void split_u(float x, uint32_t& h, uint32_t& l) {
    uint32_t hb = tf32r(x);
    h = hb;
    l = tf32r(x - __uint_as_float(hb));
}
__device__ __forceinline__ void split_f(float x, float& h, float& l) {
    uint32_t hb, lb;
    split_u(x, hb, lb);
    h = __uint_as_float(hb);
    l = __uint_as_float(lb);
}
__device__ __forceinline__ void mma8(float* c,
                                     uint32_t a0, uint32_t a1, uint32_t a2, uint32_t a3,
                                     uint32_t b0, uint32_t b1) {
    asm volatile(
        "mma.sync.aligned.m16n8k8.row.col.f32.tf32.tf32.f32 "
        "{%0,%1,%2,%3}, {%4,%5,%6,%7}, {%8,%9}, {%0,%1,%2,%3};"
        : "+f"(c[0]), "+f"(c[1]), "+f"(c[2]), "+f"(c[3])
        : "r"(a0), "r"(a1), "r"(a2), "r"(a3), "r"(b0), "r"(b1));
}
__device__ __forceinline__ uint32_t fu(float x) { return __float_as_uint(x); }
__device__ __forceinline__ void cp16(void* dst, const void* src) {
    uint32_t d = (uint32_t)__cvta_generic_to_shared(dst);
    asm volatile("cp.async.cg.shared.global [%0], [%1], 16;" :: "r"(d), "l"(src));
}
#define CP_COMMIT() asm volatile("cp.async.commit_group;")
#define CP_WAIT(n)  asm volatile("cp.async.wait_group %0;" :: "n"(n))

// ---------------------------------------------------------------------------
// GEMM core: 512 threads, 128x128 tile, BK=32, 16 warps (4x4), warp tile 32x32.
// hi/lo tf32 planes in smem (split once at STS), manual LDG double buffer.
// Mainloop: pure LDS + mma. smem = 8 * 128*36 * 4B = 147456 B.
// ---------------------------------------------------------------------------
#define GLD 36   // 36 mod 32 = 4 -> conflict-free frag LDS
#define PL  (128*GLD)

__device__ __forceinline__ void sts_split4(float* Ph, float* Pl, int idx, float4 v) {
    float4 hv, lv;
    split_f(v.x, hv.x, lv.x); split_f(v.y, hv.y, lv.y);
    split_f(v.z, hv.z, lv.z); split_f(v.w, hv.w, lv.w);
    *(float4*)&Ph[idx] = hv;
    *(float4*)&Pl[idx] = lv;
}

__device__ __forceinline__ void gemm_core512(const float* __restrict__ A,
                                             const float* __restrict__ Wm,
                                             int m0, int n0, int K,
                                             float* smem, float C[2][4][4])
{
    float* Ah = smem;            // [2][PL]
    float* Al = smem + 2*PL;
    float* Bh = smem + 4*PL;
    float* Bl = smem + 6*PL;
    int t = threadIdx.x, wid = t >> 5, lane = t & 31;
    int g = lane >> 2, tg = lane & 3;
    int wm = wid >> 2, wn = wid & 3;

#pragma unroll
    for (int i = 0; i < 2; ++i)
#pragma unroll
        for (int j = 0; j < 4; ++j) {
            C[i][j][0] = 0.f; C[i][j][1] = 0.f; C[i][j][2] = 0.f; C[i][j][3] = 0.f;
        }

    const int NS = K / 32;
    int r0 = t >> 3, c0 = (t & 7) * 4;     // r0: 0..63, c0: 0..28
    int idx0 = r0 * GLD + c0;
    int idx1 = (r0 + 64) * GLD + c0;

    float4 a0, a1, b0, b1;
    // prefetch stage 0
    a0 = *(const float4*)(A  + (size_t)(m0 + r0)      * K + c0);
    a1 = *(const float4*)(A  + (size_t)(m0 + r0 + 64) * K + c0);
    b0 = *(const float4*)(Wm + (size_t)(n0 + r0)      * K + c0);
    b1 = *(const float4*)(Wm + (size_t)(n0 + r0 + 64) * K + c0);
    sts_split4(Ah, Al, idx0, a0);
    sts_split4(Ah, Al, idx1, a1);
    sts_split4(Bh, Bl, idx0, b0);
    sts_split4(Bh, Bl, idx1, b1);

    for (int s = 0; s < NS; ++s) {
        if (s + 1 < NS) {
            int kt = (s + 1) * 32;
            a0 = *(const float4*)(A  + (size_t)(m0 + r0)      * K + kt + c0);
            a1 = *(const float4*)(A  + (size_t)(m0 + r0 + 64) * K + kt + c0);
            b0 = *(const float4*)(Wm + (size_t)(n0 + r0)      * K + kt + c0);
            b1 = *(const float4*)(Wm + (size_t)(n0 + r0 + 64) * K + kt + c0);
        }
        __syncthreads();   // STS of stage s visible

        int p = s & 1;
        const float* Ahp = Ah + p * PL;
        const float* Alp = Al + p * PL;
        const float* Bhp = Bh + p * PL;
        const float* Blp = Bl + p * PL;
#pragma unroll
        for (int kk = 0; kk < 32; kk += 8) {
            uint32_t ah[2][4], al[2][4];
#pragma unroll
            for (int mt = 0; mt < 2; ++mt) {
                int ba = (wm*32 + mt*16 + g) * GLD + kk + tg;
                ah[mt][0] = fu(Ahp[ba]);          ah[mt][1] = fu(Ahp[ba + 8*GLD]);
                ah[mt][2] = fu(Ahp[ba + 4]);      ah[mt][3] = fu(Ahp[ba + 8*GLD + 4]);
                al[mt][0] = fu(Alp[ba]);          al[mt][1] = fu(Alp[ba + 8*GLD]);
                al[mt][2] = fu(Alp[ba + 4]);      al[mt][3] = fu(Alp[ba + 8*GLD + 4]);
            }
#pragma unroll
            for (int nt = 0; nt < 4; ++nt) {
                int bb = (wn*32 + nt*8 + g) * GLD + kk + tg;
                uint32_t bh0 = fu(Bhp[bb]), bh1 = fu(Bhp[bb + 4]);
                uint32_t bl0 = fu(Blp[bb]), bl1 = fu(Blp[bb + 4]);
#pragma unroll
                for (int mt = 0; mt < 2; ++mt) {
                    mma8(C[mt][nt], ah[mt][0], ah[mt][1], ah[mt][2], ah[mt][3], bh0, bh1);
                    mma8(C[mt][nt], ah[mt][0], ah[mt][1], ah[mt][2], ah[mt][3], bl0, bl1);
                    mma8(C[mt][nt], al[mt][0], al[mt][1], al[mt][2], al[mt][3], bh0, bh1);
                }
            }
        }
        if (s + 1 < NS) {
            int p1 = (s + 1) & 1;
            sts_split4(Ah + p1*PL, Al + p1*PL, idx0, a0);
            sts_split4(Ah + p1*PL, Al + p1*PL, idx1, a1);
            sts_split4(Bh + p1*PL, Bl + p1*PL, idx0, b0);
            sts_split4(Bh + p1*PL, Bl + p1*PL, idx1, b1);
        }
    }
}

// ---------------------------------------------------------------------------
// Kernel 1: QKV GEMM.  M=4096, N=3072, K=1024. Scatter to q(x0.125)/k/v.
// ---------------------------------------------------------------------------
__global__ __launch_bounds__(512) void qkv_tc(const float* __restrict__ A,
                                              const float* __restrict__ W)
{
    extern __shared__ float sm[];
    int t = threadIdx.x, wid = t >> 5, lane = t & 31;
    int g = lane >> 2, tg = lane & 3;
    int m0 = blockIdx.y * 128, n0 = blockIdx.x * 128;
    int wm = wid >> 2, wn = wid & 3;

    float C[2][4][4];
    gemm_core512(A, W, m0, n0, ND_, sm, C);

#pragma unroll
    for (int mt = 0; mt < 2; ++mt) {
#pragma unroll
        for (int nt = 0; nt < 4; ++nt) {
            int m = m0 + wm*32 + mt*16 + g;
            int n = n0 + wn*32 + nt*8 + 2*tg;
            int part = n >> 10, rem = n & 1023;
            int h = rem >> 6, d = rem & 63;
            float sc = (part == 0) ? 0.125f : 1.0f;
            float* dst = (part == 0) ? g_q : ((part == 1) ? g_k : g_v);
            int bb0 = m >> 10, si0 = m & 1023;
            float* o0 = dst + ((size_t)(bb0*H_ + h) * L_ + si0) * D_ + d;
            *(float2*)o0 = make_float2(C[mt][nt][0]*sc, C[mt][nt][1]*sc);
            int m1 = m + 8;
            int bb1 = m1 >> 10, si1 = m1 & 1023;
            float* o1 = dst + ((size_t)(bb1*H_ + h) * L_ + si1) * D_ + d;
            *(float2*)o1 = make_float2(C[mt][nt][2]*sc, C[mt][nt][3]*sc);
        }
    }
}

// ---------------------------------------------------------------------------
// Kernel 4: output projection.  M=4096, N=1024, K=1024.
// ---------------------------------------------------------------------------
__global__ __launch_bounds__(512) void proj_tc(const float* __restrict__ Wout,
                                               const float* __restrict__ bout,
                                               float* __restrict__ out)
{
    extern __shared__ float sm[];
    int t = threadIdx.x, wid = t >> 5, lane = t & 31;
    int g = lane >> 2, tg = lane & 3;
    int m0 = blockIdx.y * 128, n0 = blockIdx.x * 128;
    int wm = wid >> 2, wn = wid & 3;

    float C[2][4][4];
    gemm_core512(g_attn, Wout, m0, n0, ND_, sm, C);

#pragma unroll
    for (int mt = 0; mt < 2; ++mt) {
#pragma unroll
        for (int nt = 0; nt < 4; ++nt) {
            int m = m0 + wm*32 + mt*16 + g;
            int n = n0 + wn*32 + nt*8 + 2*tg;
            float2 bo = *(const float2*)(bout + n);
            *(float2*)(out + (size_t)m * ND_ + n) =
                make_float2(C[mt][nt][0] + bo.x, C[mt][nt][1] + bo.y);
            *(float2*)(out + (size_t)(m + 8) * ND_ + n) =
                make_float2(C[mt][nt][2] + bo.x, C[mt][nt][3] + bo.y);
        }
    }
}

// ---------------------------------------------------------------------------
// Kernel 2: pair bias (memory-bound, unchanged).
// ---------------------------------------------------------------------------
__global__ __launch_bounds__(256) void pairbias_kernel(const float* __restrict__ z,
                                                       const float* __restrict__ Wb,
                                                       const float* __restrict__ bb)
{
    __shared__ float zs[128 * 65];
    __shared__ float wbs[16 * 64];
    __shared__ float bbs[16];
    int t = threadIdx.x;
    size_t row0 = (size_t)blockIdx.x * 128;
    const float* zp = z + row0 * 64;

    for (int f = t; f < 2048; f += 256) {
        float4 v = *(const float4*)(zp + (size_t)f * 4);
        int r = f >> 4, c = (f & 15) * 4;
        zs[r*65+c] = v.x; zs[r*65+c+1] = v.y; zs[r*65+c+2] = v.z; zs[r*65+c+3] = v.w;
    }
    for (int i = t; i < 1024; i += 256) wbs[i] = Wb[i];
    if (t < 16) bbs[t] = bb[t];
    __syncthreads();

    int j  = t & 127;
    int hb = (t >> 7) * 8;

    float4 zr[16];
#pragma unroll
    for (int c4 = 0; c4 < 16; ++c4) {
        int c = c4 * 4;
        zr[c4] = make_float4(zs[j*65+c], zs[j*65+c+1], zs[j*65+c+2], zs[j*65+c+3]);
    }
    float acc[8];
#pragma unroll
    for (int hh = 0; hh < 8; ++hh) acc[hh] = bbs[hb + hh];
#pragma unroll
    for (int c4 = 0; c4 < 16; ++c4) {
        float4 zv = zr[c4];
#pragma unroll
        for (int hh = 0; hh < 8; ++hh) {
            float4 wv = *(const float4*)(wbs + (hb + hh) * 64 + c4 * 4);
            acc[hh] += zv.x*wv.x + zv.y*wv.y + zv.z*wv.z + zv.w*wv.w;
        }
    }

    size_t bi = row0 >> 10;
    int j0 = (int)(row0 & 1023);
    int bbatch = (int)(bi >> 10);
    int irow   = (int)(bi & 1023);
#pragma unroll
    for (int hh = 0; hh < 8; ++hh) {
        int h = hb + hh;
        g_bias[((size_t)(bbatch * H_ + h) * L_ + irow) * L_ + j0 + j] = acc[hh];
    }
}

// ---------------------------------------------------------------------------
// Kernel 3: flash attention, tensor cores, kv tiles of 32, cp.async double
// buffer on K/V/bias.  Block = (b, h, 128 q rows); 8 warps x 16 q-rows.
// smem = 107520 B -> 2 CTAs/SM.  Lower regs via S[4][4] (32-col kv tiles).
// ---------------------------------------------------------------------------
#define LQ 68   // conflict-free for (g*ld + tg) pattern
#define LV 72   // conflict-free for (tg*ld + g) pattern
#define LP 36
__global__ __launch_bounds__(256, 2) void attn_tc()
{
    extern __shared__ float sm[];
    float* Qs = sm;                        // 128*68        = 8704
    float* Ks = Qs + 128*LQ;               // 2 * 32*68     = 4352
    float* Vs = Ks + 2*32*LQ;              // 2 * 32*72     = 4608
    float* Ps = Vs + 2*32*LV;              // 2 * 128*36    = 9216

    int t = threadIdx.x, wid = t >> 5, lane = t & 31;
    int g = lane >> 2, tg = lane & 3;
    int x = blockIdx.x;
    int qb = x & 7, h = (x >> 3) & 15, b = x >> 7;
    size_t bh = (size_t)b * H_ + h;
    int qw = wid * 16;

    const float* qp = g_q + (bh * L_ + (size_t)qb * 128) * D_;
    const float* kbase = g_k + bh * L_ * D_;
    const float* vbase = g_v + bh * L_ * D_;
    const float* bp = g_bias + (bh * L_ + (size_t)qb * 128) * L_;

    // load Q (fp32)
    for (int i = t; i < 2048; i += 256) {
        int r = i >> 4, c = (i & 15) * 4;
        *(float4*)&Qs[r*LQ + c] = *(const float4*)(qp + r * 64 + c);
    }

    float O[8][4];
#pragma unroll
    for (int i = 0; i < 8; ++i) { O[i][0]=0.f; O[i][1]=0.f; O[i][2]=0.f; O[i][3]=0.f; }
    float mi0 = -1e30f, mi1 = -1e30f, li0 = 0.f, li1 = 0.f;

    // prefetch tile 0 into buf 0
    {
        const float* kp = kbase;
        const float* vp = vbase;
#pragma unroll
        for (int j = 0; j < 2; ++j) {
            int i = t + j * 256;
            int r = i >> 4, c = (i & 15) * 4;
            cp16(&Ks[r*LQ + c], kp + r * 64 + c);
            cp16(&Vs[r*LV + c], vp + r * 64 + c);
        }
#pragma unroll
        for (int j = 0; j < 4; ++j) {
            int i = t + j * 256;
            int r = i >> 3, c = (i & 7) * 4;
            cp16(&Ps[r*LP + c], bp + (size_t)r * L_ + c);
        }
        CP_COMMIT();
    }

    for (int kb = 0; kb < 32; ++kb) {
        int p = kb & 1;
        __syncthreads();   // all warps done with buf p^1 (prev PV reads)
        if (kb + 1 < 32) {
            int p1 = p ^ 1;
            const float* kp = kbase + (size_t)(kb + 1) * 32 * D_;
            const float* vp = vbase + (size_t)(kb + 1) * 32 * D_;
#pragma unroll
            for (int j = 0; j < 2; ++j) {
                int i = t + j * 256;
                int r = i >> 4, c = (i & 15) * 4;
                cp16(&Ks[p1*32*LQ + r*LQ + c], kp + r * 64 + c);
                cp16(&Vs[p1*32*LV + r*LV + c], vp + r * 64 + c);
            }
#pragma unroll
            for (int j = 0; j < 4; ++j) {
                int i = t + j * 256;
                int r = i >> 3, c = (i & 7) * 4;
                cp16(&Ps[p1*128*LP + r*LP + c],
                     bp + (size_t)r * L_ + (kb + 1) * 32 + c);
            }
            CP_COMMIT();
            CP_WAIT(1);
        } else {
            CP_WAIT(0);
        }
        __syncthreads();   // tile kb visible to all

        const float* Kp = Ks + p*32*LQ;
        const float* Vp = Vs + p*32*LV;
        float*       Pp = Ps + p*128*LP;

        // S = Q K^T  (16 x 32 per warp)
        float S[4][4];
#pragma unroll
        for (int i = 0; i < 4; ++i) { S[i][0]=0.f; S[i][1]=0.f; S[i][2]=0.f; S[i][3]=0.f; }
#pragma unroll
        for (int kk = 0; kk < 64; kk += 8) {
            int qa = (qw + g) * LQ + kk + tg;
            uint32_t ah0,al0,ah1,al1,ah2,al2,ah3,al3;
            split_u(Qs[qa],           ah0, al0);
            split_u(Qs[qa + 8*LQ],    ah1, al1);
            split_u(Qs[qa + 4],       ah2, al2);
            split_u(Qs[qa + 8*LQ+4],  ah3, al3);
#pragma unroll
            for (int nt = 0; nt < 4; ++nt) {
                int ka = (nt*8 + g) * LQ + kk + tg;
                uint32_t bh0, bl0, bh1, bl1;
                split_u(Kp[ka],     bh0, bl0);
                split_u(Kp[ka + 4], bh1, bl1);
                mma8(S[nt], ah0, ah1, ah2, ah3, bh0, bh1);
                mma8(S[nt], ah0, ah1, ah2, ah3, bl0, bl1);
                mma8(S[nt], al0, al1, al2, al3, bh0, bh1);
            }
        }

        // bias add + online softmax (thread owns rows qw+g, qw+g+8)
        float rm0 = -1e30f, rm1 = -1e30f;
#pragma unroll
        for (int nt = 0; nt < 4; ++nt) {
            float2 b0 = *(const float2*)&Pp[(qw + g) * LP + nt*8 + 2*tg];
            float2 b1 = *(const float2*)&Pp[(qw + g + 8) * LP + nt*8 + 2*tg];
            S[nt][0] += b0.x; S[nt][1] += b0.y;
            S[nt][2] += b1.x; S[nt][3] += b1.y;
            rm0 = fmaxf(rm0, fmaxf(S[nt][0], S[nt][1]));
            rm1 = fmaxf(rm1, fmaxf(S[nt][2], S[nt][3]));
        }
        rm0 = fmaxf(rm0, __shfl_xor_sync(0xffffffffu, rm0, 1));
        rm0 = fmaxf(rm0, __shfl_xor_sync(0xffffffffu, rm0, 2));
        rm1 = fmaxf(rm1, __shfl_xor_sync(0xffffffffu, rm1, 1));
        rm1 = fmaxf(rm1, __shfl_xor_sync(0xffffffffu, rm1, 2));
        float nm0 = fmaxf(mi0, rm0), nm1 = fmaxf(mi1, rm1);
        float cr0 = __expf(mi0 - nm0), cr1 = __expf(mi1 - nm1);
        float rs0 = 0.f, rs1 = 0.f;
#pragma unroll
        for (int nt = 0; nt < 4; ++nt) {
            S[nt][0] = __expf(S[nt][0] - nm0);
            S[nt][1] = __expf(S[nt][1] - nm0);
            S[nt][2] = __expf(S[nt][2] - nm1);
            S[nt][3] = __expf(S[nt][3] - nm1);
            rs0 += S[nt][0] + S[nt][1];
            rs1 += S[nt][2] + S[nt][3];
        }
        rs0 += __shfl_xor_sync(0xffffffffu, rs0, 1);
        rs0 += __shfl_xor_sync(0xffffffffu, rs0, 2);
        rs1 += __shfl_xor_sync(0xffffffffu, rs1, 1);
        rs1 += __shfl_xor_sync(0xffffffffu, rs1, 2);
        li0 = li0 * cr0 + rs0;  mi0 = nm0;
        li1 = li1 * cr1 + rs1;  mi1 = nm1;
#pragma unroll
        for (int nt = 0; nt < 8; ++nt) {
            O[nt][0] *= cr0; O[nt][1] *= cr0;
            O[nt][2] *= cr1; O[nt][3] *= cr1;
        }
        // write P over the bias staging slots (same thread-owned slots)
#pragma unroll
        for (int nt = 0; nt < 4; ++nt) {
            *(float2*)&Pp[(qw + g) * LP + nt*8 + 2*tg]     = make_float2(S[nt][0], S[nt][1]);
            *(float2*)&Pp[(qw + g + 8) * LP + nt*8 + 2*tg] = make_float2(S[nt][2], S[nt][3]);
        }
        __syncwarp();   // warp reads only its own strip of P

        // O += P V   (kv is the k-dim: 32)
#pragma unroll
        for (int kk = 0; kk < 32; kk += 8) {
            int pa = (qw + g) * LP + kk + tg;
            uint32_t ah0,al0,ah1,al1,ah2,al2,ah3,al3;
            split_u(Pp[pa],           ah0, al0);
            split_u(Pp[pa + 8*LP],    ah1, al1);
            split_u(Pp[pa + 4],       ah2, al2);
            split_u(Pp[pa + 8*LP+4],  ah3, al3);
#pragma unroll
            for (int nt = 0; nt < 8; ++nt) {
                int va = (kk + tg) * LV + nt*8 + g;
                uint32_t bh0, bl0, bh1, bl1;
                split_u(Vp[va],          bh0, bl0);
                split_u(Vp[va + 4*LV],   bh1, bl1);
                mma8(O[nt], ah0, ah1, ah2, ah3, bh0, bh1);
                mma8(O[nt], ah0, ah1, ah2, ah3, bl0, bl1);
                mma8(O[nt], al0, al1, al2, al3, bh0, bh1);
            }
        }
    }

    float inv0 = 1.0f / li0, inv1 = 1.0f / li1;
    int q0 = qb * 128 + qw + g;
    float* ob = g_attn + ((size_t)b * L_ + q0) * ND_ + h * D_;
#pragma unroll
    for (int nt = 0; nt < 8; ++nt) {
        *(float2*)(ob + nt*8 + 2*tg) =
            make_float2(O[nt][0]*inv0, O[nt][1]*inv0);
        *(float2*)(ob + (size_t)8 * ND_ + nt*8 + 2*tg) =
            make_float2(O[nt][2]*inv1, O[nt][3]*inv1);
    }
}

// ---------------------------------------------------------------------------
extern "C" void kernel_launch(void* const* d_in, const int* in_sizes, int n_in,
                              void* d_out, int out_size)
{
    const float* s      = (const float*)d_in[0];
    const float* z      = (const float*)d_in[1];
    const float* W_qkv  = (const float*)d_in[2];
    const float* W_bias = (const float*)d_in[3];
    const float* b_bias = (const float*)d_in[4];
    const float* W_out  = (const float*)d_in[5];
    const float* b_out  = (const float*)d_in[6];
    float* out = (float*)d_out;

    (void)in_sizes; (void)n_in; (void)out_size;

    const int gemm_smem = 8 * PL * sizeof(float);   // 147456
    const int attn_smem = (128*LQ + 2*32*LQ + 2*32*LV + 2*128*LP) * sizeof(float); // 107520

    cudaFuncSetAttribute(qkv_tc,  cudaFuncAttributeMaxDynamicSharedMemorySize, gemm_smem);
    cudaFuncSetAttribute(proj_tc, cudaFuncAttributeMaxDynamicSharedMemorySize, gemm_smem);
    cudaFuncSetAttribute(attn_tc, cudaFuncAttributeMaxDynamicSharedMemorySize, attn_smem);

    dim3 g1(24, 32);
    qkv_tc<<<g1, 512, gemm_smem>>>(s, W_qkv);

    pairbias_kernel<<<32768, 256>>>(z, W_bias, b_bias);

    attn_tc<<<512, 256, attn_smem>>>();

    dim3 g4(8, 32);
    proj_tc<<<g4, 512, gemm_smem>>>(W_out, b_out, out);
}